// round 1
// baseline (speedup 1.0000x reference)
#include <cuda_runtime.h>
#include <cstdint>

// DARTS layer as fused on-the-fly GEMM:
//   out[b,j] = sum_{i,k} prim_k(x[b,i]) * w[i,j,k],  w = softmax(alphas)*coeffs
// => C[65536,64] = A[65536,512] @ B[512,64], A generated from x, tf32 mma.sync.

#define NI 64
#define NJ 64
#define NOPS 8
#define M_CTA 512
#define THREADS 512
#define PSTRIDE 36   // 36 mod 32 = 4 -> A-frag smem bank = lane (conflict free)

// W in mma B-fragment order: [kstep s=0..63][nfrag f=0..7][lane 0..31][slot 0..1]
__device__ float g_Wfrag[64 * 8 * 32 * 2];

__device__ __forceinline__ uint32_t f2tf32(float f) {
    uint32_t r;
    asm("cvt.rna.tf32.f32 %0, %1;" : "=r"(r) : "f"(f));
    return r;
}

__device__ __forceinline__ void mma_tf32(float c[4], const uint32_t a[4],
                                         uint32_t b0, uint32_t b1) {
    asm volatile(
        "mma.sync.aligned.m16n8k8.row.col.f32.tf32.tf32.f32 "
        "{%0,%1,%2,%3}, {%4,%5,%6,%7}, {%8,%9}, {%0,%1,%2,%3};"
        : "+f"(c[0]), "+f"(c[1]), "+f"(c[2]), "+f"(c[3])
        : "r"(a[0]), "r"(a[1]), "r"(a[2]), "r"(a[3]), "r"(b0), "r"(b1));
}

// ---------------------------------------------------------------------------
// Kernel 1: build W fragments (tiny: 4096 threads)
// ---------------------------------------------------------------------------
__global__ void prep_w_kernel(const float* __restrict__ alphas,
                              const float* __restrict__ coeffs) {
    int id = blockIdx.x * blockDim.x + threadIdx.x;
    if (id >= NI * NJ) return;
    int i = id >> 6;
    int j = id & 63;
    const float* a = alphas + (size_t)id * NOPS;
    const float* c = coeffs + (size_t)id * NOPS;

    float av[8], m = -1e30f;
#pragma unroll
    for (int k = 0; k < 8; ++k) { av[k] = a[k]; m = fmaxf(m, av[k]); }
    float e[8], s = 0.f;
#pragma unroll
    for (int k = 0; k < 8; ++k) { e[k] = __expf(av[k] - m); s += e[k]; }
    float inv = 1.0f / s;

#pragma unroll
    for (int k = 0; k < 8; ++k) {
        // op 0 ("none") contributes zero (A column is zero too); store 0 for cleanliness
        float w = (k == 0) ? 0.0f : e[k] * inv * c[k];
        int f = j >> 3;                        // n-fragment
        int lane = ((j & 7) << 2) | (k & 3);   // b-frag: col = lane/4, row(k) = lane%4 (+4 for slot 1)
        int slot = k >> 2;
        g_Wfrag[((i * 8 + f) * 32 + lane) * 2 + slot] = __uint_as_float(f2tf32(w));
    }
}

// ---------------------------------------------------------------------------
// Kernel 2: fused prim-generation + tf32 GEMM
//   128 CTAs x 512 threads; 16 warps, each warp: m32 x n64, K=512 (64 k-steps)
// ---------------------------------------------------------------------------
__global__ void __launch_bounds__(THREADS, 1)
darts_gemm_kernel(const float* __restrict__ x, float* __restrict__ out) {
    extern __shared__ float sm[];
    float* sW = sm;                  // 32768 floats (128 KB)
    float* sP = sm + 32768;          // 512 * 36 floats (73.7 KB)

    int tid = threadIdx.x;
    int lane = tid & 31;
    int warp = tid >> 5;
    int ctaRow0 = blockIdx.x * M_CTA;
    int warpRow = warp * 32;
    int qrow = lane >> 2;
    int qcol = lane & 3;

    // cooperative load of all W fragments into smem
    {
        const float4* gw4 = (const float4*)g_Wfrag;
        float4* sw4 = (float4*)sW;
#pragma unroll
        for (int idx = tid; idx < 8192; idx += THREADS) sw4[idx] = gw4[idx];
    }
    __syncthreads();

    float acc[2][8][4];
#pragma unroll
    for (int m = 0; m < 2; ++m)
#pragma unroll
        for (int f = 0; f < 8; ++f)
#pragma unroll
            for (int q = 0; q < 4; ++q) acc[m][f][q] = 0.f;

    const float4* xrow = (const float4*)(x + (size_t)(ctaRow0 + tid) * NI);

    // 16 chunks of 4 input features; each feature = one k8 step
    for (int chunk = 0; chunk < 16; ++chunk) {
        // ---- stage primitives for this thread's row (own warp reads only own rows)
        float4 xv = xrow[chunk];
        float xs[4] = {xv.x, xv.y, xv.z, xv.w};
#pragma unroll
        for (int u = 0; u < 4; ++u) {
            float xx = xs[u];
            float x2 = xx * xx;
            float x3 = x2 * xx;
            float ex = __expf(xx);
            float lg = __logf(xx);
            float rc;
            asm("rcp.approx.f32 %0, %1;" : "=f"(rc) : "f"(xx));
            float sn = __sinf(xx);
            float* p = sP + tid * PSTRIDE + u * 8;
            p[0] = 0.0f;                                // none
            p[1] = __uint_as_float(f2tf32(xx));         // linear
            p[2] = __uint_as_float(f2tf32(x2));         // x^2
            p[3] = __uint_as_float(f2tf32(x3));         // x^3
            p[4] = __uint_as_float(f2tf32(ex));         // exp
            p[5] = __uint_as_float(f2tf32(lg));         // ln
            p[6] = __uint_as_float(f2tf32(rc));         // 1/x
            p[7] = __uint_as_float(f2tf32(sn));         // sin
        }
        __syncwarp();

        // ---- 4 k-steps of mma
#pragma unroll
        for (int s4 = 0; s4 < 4; ++s4) {
            int s = chunk * 4 + s4;
            uint32_t a[2][4];
#pragma unroll
            for (int m = 0; m < 2; ++m) {
                int r0 = warpRow + m * 16 + qrow;
                const float* base = sP + s4 * 8 + qcol;
                a[m][0] = __float_as_uint(base[r0 * PSTRIDE]);
                a[m][1] = __float_as_uint(base[(r0 + 8) * PSTRIDE]);
                a[m][2] = __float_as_uint(base[r0 * PSTRIDE + 4]);
                a[m][3] = __float_as_uint(base[(r0 + 8) * PSTRIDE + 4]);
            }
            const float2* wbase = (const float2*)sW + s * 256 + lane;
#pragma unroll
            for (int f = 0; f < 8; ++f) {
                float2 b = wbase[f * 32];
                uint32_t b0 = __float_as_uint(b.x);
                uint32_t b1 = __float_as_uint(b.y);
                mma_tf32(acc[0][f], a[0], b0, b1);
                mma_tf32(acc[1][f], a[1], b0, b1);
            }
        }
        __syncwarp();  // before next chunk overwrites sP
    }

    // ---- epilogue: c0/c1 -> (row, 2*qcol..+1), c2/c3 -> (row+8, ...)
#pragma unroll
    for (int m = 0; m < 2; ++m) {
        int r = ctaRow0 + warpRow + m * 16 + qrow;
#pragma unroll
        for (int f = 0; f < 8; ++f) {
            int col = f * 8 + qcol * 2;
            *(float2*)(out + (size_t)r * NJ + col) =
                make_float2(acc[m][f][0], acc[m][f][1]);
            *(float2*)(out + (size_t)(r + 8) * NJ + col) =
                make_float2(acc[m][f][2], acc[m][f][3]);
        }
    }
}

// ---------------------------------------------------------------------------
extern "C" void kernel_launch(void* const* d_in, const int* in_sizes, int n_in,
                              void* d_out, int out_size) {
    const float* x      = (const float*)d_in[0];   // [65536, 64]
    const float* alphas = (const float*)d_in[1];   // [64, 64, 8]
    const float* coeffs = (const float*)d_in[2];   // [64, 64, 8]
    float* out = (float*)d_out;                    // [65536, 64]

    const int SMEM = (32768 + M_CTA * PSTRIDE) * (int)sizeof(float);  // 204800 B
    cudaFuncSetAttribute((const void*)darts_gemm_kernel,
                         cudaFuncAttributeMaxDynamicSharedMemorySize, SMEM);

    prep_w_kernel<<<16, 256>>>(alphas, coeffs);
    darts_gemm_kernel<<<65536 / M_CTA, THREADS, SMEM>>>(x, out);
}

// round 2
// speedup vs baseline: 1.0111x; 1.0111x over previous
#include <cuda_runtime.h>
#include <cstdint>

// DARTS layer as fused on-the-fly GEMM:
//   out[b,j] = sum_{i,k} prim_k(x[b,i]) * w[i,j,k],  w = softmax(alphas)*coeffs
// => C[65536,64] = A[65536,512] @ B[512,64], A generated from x, tf32 mma.sync.

#define NI 64
#define NJ 64
#define NOPS 8
#define M_CTA 512
#define THREADS 512
#define PSTRIDE 36   // 36 mod 32 = 4 -> A-frag smem bank = lane (conflict free)

// W in mma B-fragment order: [kstep s=0..63][nfrag f=0..7][lane 0..31][slot 0..1]
__device__ float g_Wfrag[64 * 8 * 32 * 2];

__device__ __forceinline__ uint32_t f2tf32(float f) {
    uint32_t r;
    asm("cvt.rna.tf32.f32 %0, %1;" : "=r"(r) : "f"(f));
    return r;
}

__device__ __forceinline__ void mma_tf32(float c[4], const uint32_t a[4],
                                         uint32_t b0, uint32_t b1) {
    asm volatile(
        "mma.sync.aligned.m16n8k8.row.col.f32.tf32.tf32.f32 "
        "{%0,%1,%2,%3}, {%4,%5,%6,%7}, {%8,%9}, {%0,%1,%2,%3};"
        : "+f"(c[0]), "+f"(c[1]), "+f"(c[2]), "+f"(c[3])
        : "r"(a[0]), "r"(a[1]), "r"(a[2]), "r"(a[3]), "r"(b0), "r"(b1));
}

// ---------------------------------------------------------------------------
// Kernel 1: build W fragments (tiny: 4096 threads)
// ---------------------------------------------------------------------------
__global__ void prep_w_kernel(const float* __restrict__ alphas,
                              const float* __restrict__ coeffs) {
    int id = blockIdx.x * blockDim.x + threadIdx.x;
    if (id >= NI * NJ) return;
    int i = id >> 6;
    int j = id & 63;
    const float* a = alphas + (size_t)id * NOPS;
    const float* c = coeffs + (size_t)id * NOPS;

    float av[8], m = -1e30f;
#pragma unroll
    for (int k = 0; k < 8; ++k) { av[k] = a[k]; m = fmaxf(m, av[k]); }
    float e[8], s = 0.f;
#pragma unroll
    for (int k = 0; k < 8; ++k) { e[k] = __expf(av[k] - m); s += e[k]; }
    float inv = 1.0f / s;

#pragma unroll
    for (int k = 0; k < 8; ++k) {
        // op 0 ("none") contributes zero (A column is zero too); store 0 for cleanliness
        float w = (k == 0) ? 0.0f : e[k] * inv * c[k];
        int f = j >> 3;                        // n-fragment
        int lane = ((j & 7) << 2) | (k & 3);   // b-frag: col = lane/4, row(k) = lane%4 (+4 for slot 1)
        int slot = k >> 2;
        g_Wfrag[((i * 8 + f) * 32 + lane) * 2 + slot] = __uint_as_float(f2tf32(w));
    }
}

// ---------------------------------------------------------------------------
// Kernel 2: fused prim-generation + tf32 GEMM
//   128 CTAs x 512 threads; 16 warps, each warp: m32 x n64, K=512 (64 k-steps)
// ---------------------------------------------------------------------------
__global__ void __launch_bounds__(THREADS, 1)
darts_gemm_kernel(const float* __restrict__ x, float* __restrict__ out) {
    extern __shared__ float sm[];
    float* sW = sm;                  // 32768 floats (128 KB)
    float* sP = sm + 32768;          // 512 * 36 floats (73.7 KB)

    int tid = threadIdx.x;
    int lane = tid & 31;
    int warp = tid >> 5;
    int ctaRow0 = blockIdx.x * M_CTA;
    int warpRow = warp * 32;
    int qrow = lane >> 2;
    int qcol = lane & 3;

    // cooperative load of all W fragments into smem
    {
        const float4* gw4 = (const float4*)g_Wfrag;
        float4* sw4 = (float4*)sW;
#pragma unroll
        for (int idx = tid; idx < 8192; idx += THREADS) sw4[idx] = gw4[idx];
    }
    __syncthreads();

    float acc[2][8][4];
#pragma unroll
    for (int m = 0; m < 2; ++m)
#pragma unroll
        for (int f = 0; f < 8; ++f)
#pragma unroll
            for (int q = 0; q < 4; ++q) acc[m][f][q] = 0.f;

    const float4* xrow = (const float4*)(x + (size_t)(ctaRow0 + tid) * NI);

    // 16 chunks of 4 input features; each feature = one k8 step
    for (int chunk = 0; chunk < 16; ++chunk) {
        // ---- stage primitives for this thread's row (own warp reads only own rows)
        float4 xv = xrow[chunk];
        float xs[4] = {xv.x, xv.y, xv.z, xv.w};
#pragma unroll
        for (int u = 0; u < 4; ++u) {
            float xx = xs[u];
            float x2 = xx * xx;
            float x3 = x2 * xx;
            float ex = __expf(xx);
            float lg = __logf(xx);
            float rc;
            asm("rcp.approx.f32 %0, %1;" : "=f"(rc) : "f"(xx));
            float sn = __sinf(xx);
            float* p = sP + tid * PSTRIDE + u * 8;
            p[0] = 0.0f;                                // none
            p[1] = __uint_as_float(f2tf32(xx));         // linear
            p[2] = __uint_as_float(f2tf32(x2));         // x^2
            p[3] = __uint_as_float(f2tf32(x3));         // x^3
            p[4] = __uint_as_float(f2tf32(ex));         // exp
            p[5] = __uint_as_float(f2tf32(lg));         // ln
            p[6] = __uint_as_float(f2tf32(rc));         // 1/x
            p[7] = __uint_as_float(f2tf32(sn));         // sin
        }
        __syncwarp();

        // ---- 4 k-steps of mma
#pragma unroll
        for (int s4 = 0; s4 < 4; ++s4) {
            int s = chunk * 4 + s4;
            uint32_t a[2][4];
#pragma unroll
            for (int m = 0; m < 2; ++m) {
                int r0 = warpRow + m * 16 + qrow;
                const float* base = sP + s4 * 8 + qcol;
                a[m][0] = __float_as_uint(base[r0 * PSTRIDE]);
                a[m][1] = __float_as_uint(base[(r0 + 8) * PSTRIDE]);
                a[m][2] = __float_as_uint(base[r0 * PSTRIDE + 4]);
                a[m][3] = __float_as_uint(base[(r0 + 8) * PSTRIDE + 4]);
            }
            const float2* wbase = (const float2*)sW + s * 256 + lane;
#pragma unroll
            for (int f = 0; f < 8; ++f) {
                float2 b = wbase[f * 32];
                uint32_t b0 = __float_as_uint(b.x);
                uint32_t b1 = __float_as_uint(b.y);
                mma_tf32(acc[0][f], a[0], b0, b1);
                mma_tf32(acc[1][f], a[1], b0, b1);
            }
        }
        __syncwarp();  // before next chunk overwrites sP
    }

    // ---- epilogue: c0/c1 -> (row, 2*qcol..+1), c2/c3 -> (row+8, ...)
#pragma unroll
    for (int m = 0; m < 2; ++m) {
        int r = ctaRow0 + warpRow + m * 16 + qrow;
#pragma unroll
        for (int f = 0; f < 8; ++f) {
            int col = f * 8 + qcol * 2;
            *(float2*)(out + (size_t)r * NJ + col) =
                make_float2(acc[m][f][0], acc[m][f][1]);
            *(float2*)(out + (size_t)(r + 8) * NJ + col) =
                make_float2(acc[m][f][2], acc[m][f][3]);
        }
    }
}

// ---------------------------------------------------------------------------
extern "C" void kernel_launch(void* const* d_in, const int* in_sizes, int n_in,
                              void* d_out, int out_size) {
    const float* x      = (const float*)d_in[0];   // [65536, 64]
    const float* alphas = (const float*)d_in[1];   // [64, 64, 8]
    const float* coeffs = (const float*)d_in[2];   // [64, 64, 8]
    float* out = (float*)d_out;                    // [65536, 64]

    const int SMEM = (32768 + M_CTA * PSTRIDE) * (int)sizeof(float);  // 204800 B
    cudaFuncSetAttribute((const void*)darts_gemm_kernel,
                         cudaFuncAttributeMaxDynamicSharedMemorySize, SMEM);

    prep_w_kernel<<<16, 256>>>(alphas, coeffs);
    darts_gemm_kernel<<<65536 / M_CTA, THREADS, SMEM>>>(x, out);
}